// round 14
// baseline (speedup 1.0000x reference)
#include <cuda_runtime.h>
#include <cuda_fp16.h>
#include <cstdint>

#define NB 2
#define NS 2048
#define ND 4096
#define NH 16
#define NHD 256

#define BK 64                    // K halfs per tile = 128B SW128 row
#define STAGE_M 16384            // one 128-row x 128B matrix
#define STAGE_SZ (2*STAGE_M)     // A + B = 32KB
#define NSTAGE 3
#define SMEM_SZ (NSTAGE*STAGE_SZ)   // 98304 -> 2 CTAs/SM

// ---------------- scratch (__device__ globals; no allocation) ----------------
static __device__ __half g_hid  [(size_t)NB*NS*ND];     // fp16 hidden
static __device__ __half g_wqkvT[(size_t)3*ND*ND];      // [3D, D] fp16
static __device__ __half g_woutT[(size_t)ND*ND];        // [D, D] fp16
static __device__ __half g_q    [(size_t)NB*NH*NS*NHD]; // [B,H,S,hd] fp16 (roped)
static __device__ __half g_k    [(size_t)NB*NH*NS*NHD]; // [B,H,S,hd] fp16 (roped)
static __device__ __half g_vT   [(size_t)NB*NH*NHD*NS]; // [B,H,hd,S] fp16
static __device__ float  g_sc   [(size_t)NB*NH*NS*NS];  // scores fp32
static __device__ __half g_p    [(size_t)NB*NH*NS*NS];  // probs fp16
static __device__ __half g_at   [(size_t)NB*NS*ND];     // [B,S,D] fp16

// ---------------- helpers ----------------
__device__ __forceinline__ void mmaop(float* c, const unsigned* a, const unsigned* b){
  asm volatile(
    "mma.sync.aligned.m16n8k16.row.col.f32.f16.f16.f32 "
    "{%0,%1,%2,%3},{%4,%5,%6,%7},{%8,%9},{%0,%1,%2,%3};\n"
    : "+f"(c[0]),"+f"(c[1]),"+f"(c[2]),"+f"(c[3])
    : "r"(a[0]),"r"(a[1]),"r"(a[2]),"r"(a[3]),"r"(b[0]),"r"(b[1]));
}
__device__ __forceinline__ void ldsm4(unsigned addr, unsigned* r){
  asm volatile("ldmatrix.sync.aligned.m8n8.x4.shared.b16 {%0,%1,%2,%3}, [%4];"
    : "=r"(r[0]),"=r"(r[1]),"=r"(r[2]),"=r"(r[3]) : "r"(addr));
}
__device__ __forceinline__ void cpa16(unsigned dst, const void* g){
  asm volatile("cp.async.cg.shared.global [%0],[%1],16;\n"::"r"(dst),"l"(g));
}
#define CP_COMMIT() asm volatile("cp.async.commit_group;\n")
#define CP_WAIT1()  asm volatile("cp.async.wait_group 1;\n")
__device__ __forceinline__ unsigned smem_u32(const void* p){
  unsigned a; asm("{ .reg .u64 t; cvta.to.shared.u64 t, %1; cvt.u32.u64 %0, t; }":"=r"(a):"l"(p));
  return a;
}
__device__ __forceinline__ void st2(float* p, float x, float y){
  *(float2*)p = make_float2(x,y);
}
__device__ __forceinline__ void st2(__half* p, float x, float y){
  *(__half2*)p = __floats2half2_rn(x,y);
}

// ============================================================================
// fp16 GEMM via mma.sync(m16n8k16) + ldmatrix: C = A[M,K] * B[N,K]^T, K-major
// fp16 in, fp32 accumulate. CTA 128x128 (8 warps, 64x32 warp tile), BK=64,
// SW128 swizzle, 3-stage cp.async, one __syncthreads per tile.
// causal==1: skip bn>bm.  causal==2: kend=(bm+1)*128.
// epi==1: QKV rope-split epilogue -> writes qo/ko (roped, [B,H,S,hd]) and
//         vo (transposed, [B,H,hd,S]); C unused.
// else:   C offset = (z/cdiv)*cs1 + (z%cdiv)*cs2.
// ============================================================================
template<typename CT>
__global__ void __launch_bounds__(256,2) gemm_fp16(
  const __half* __restrict__ A, const __half* __restrict__ B, CT* __restrict__ C,
  int K,int lda,int ldb,int ldc,
  long long sA,long long sB,long long cs1,long long cs2,int cdiv,
  int causal,int epi,
  const int* __restrict__ pos, __half* __restrict__ qo,
  __half* __restrict__ ko, __half* __restrict__ vo)
{
  const int bn=blockIdx.x, bm=blockIdx.y, z=blockIdx.z;
  if(causal==1 && bn>bm) return;
  int kend=K;
  if(causal==2){ int ke=(bm+1)*128; if(ke<kend) kend=ke; }
  const int nk = kend>>6;            // >= 2 for every launch here

  extern __shared__ float smem[];
  const unsigned sb = smem_u32(smem);

  const int tid=threadIdx.x, warp=tid>>5, lane=tid&31;
  const int wm=warp>>2, wn=warp&3;           // 2x4 warp grid; warp tile 64x32
  const int gq=lane>>2, tg=lane&3;

  const __half* Ab = A + (long long)z*sA + (long long)(bm*128)*lda;
  const __half* Bb = B + (long long)z*sB + (long long)(bn*128)*ldb;

  // staging: 1024 16B-chunks per matrix; thread t covers chunks {t,+256,+512,+768}
  const __half* gA[4]; const __half* gB[4]; unsigned sAo[4];
#pragma unroll
  for(int i=0;i<4;i++){
    int q=i*256+tid, row=q>>3, c=q&7;
    sAo[i] = (unsigned)(row*128 + ((c ^ (row&7))<<4));   // SW128
    gA[i]=Ab + (long long)row*lda + c*8;
    gB[i]=Bb + (long long)row*ldb + c*8;
  }

  auto stage=[&](int kt,int s){
    unsigned base = sb + s*STAGE_SZ;
#pragma unroll
    for(int i=0;i<4;i++) cpa16(base + sAo[i],           gA[i] + kt*BK);
#pragma unroll
    for(int i=0;i<4;i++) cpa16(base + STAGE_M + sAo[i], gB[i] + kt*BK);
  };

  // ldmatrix per-lane row constants
  const int lrow = lane & 15;
  const unsigned klane = lane >> 4;
  unsigned ar128[4], ar7[4], br128[2], br7[2];
#pragma unroll
  for(int mi=0;mi<4;mi++){
    int r = wm*64 + mi*16 + lrow;
    ar128[mi] = r*128; ar7[mi] = r&7;
  }
#pragma unroll
  for(int p=0;p<2;p++){
    int r = wn*32 + p*16 + lrow;
    br128[p] = r*128 + STAGE_M; br7[p] = r&7;
  }

  float acc[4][4][4];
#pragma unroll
  for(int i=0;i<4;i++)
#pragma unroll
    for(int j=0;j<4;j++)
#pragma unroll
      for(int l=0;l<4;l++) acc[i][j][l]=0.f;

  stage(0,0); CP_COMMIT();
  stage(1,1); CP_COMMIT();

  for(int kt=0; kt<nk; ++kt){
    CP_WAIT1();
    __syncthreads();

    if(kt+2<nk) stage(kt+2,(kt+2)%3);
    CP_COMMIT();

    const unsigned base = sb + (unsigned)(kt%3)*STAGE_SZ;
#pragma unroll
    for(int ks=0;ks<4;ks++){
      const unsigned ck = ks*2 + klane;
      unsigned a[4][4], br[2][4];
#pragma unroll
      for(int mi=0;mi<4;mi++)
        ldsm4(base + ar128[mi] + (((ck ^ ar7[mi]))<<4), a[mi]);
#pragma unroll
      for(int p=0;p<2;p++)
        ldsm4(base + br128[p] + (((ck ^ br7[p]))<<4), br[p]);
      unsigned b[4][2];
#pragma unroll
      for(int p=0;p<2;p++){
        b[2*p  ][0]=br[p][0]; b[2*p  ][1]=br[p][2];
        b[2*p+1][0]=br[p][1]; b[2*p+1][1]=br[p][3];
      }
#pragma unroll
      for(int mi=0;mi<4;mi++)
#pragma unroll
        for(int ni=0;ni<4;ni++)
          mmaop(acc[mi][ni], a[mi], b[ni]);
    }
  }

  if(epi){
    // ---- fused rope/split epilogue (QKV GEMM) ----
    const int cbase = bn*128;
    const int tensor = cbase >> 12;          // 0:q 1:k 2:v
    const int h = (cbase >> 8) & (NH-1);
#pragma unroll
    for(int mi=0;mi<4;mi++){
      int r0 = bm*128 + wm*64 + mi*16 + gq;  // global row; r0+8 same b
      int b0 = r0 >> 11, s0 = r0 & (NS-1);
      int p0 = pos[b0*NS+s0], p1 = pos[b0*NS+s0+8];
      const long long zz = (long long)(b0*NH + h);
#pragma unroll
      for(int ni=0;ni<4;ni++){
        int c0 = cbase + wn*32 + ni*8 + tg*2;   // even: rope pair (c0,c0+1)
        int hcol = c0 & (NHD-1);
        float x0=acc[mi][ni][0], y0=acc[mi][ni][1];   // row s0
        float x1=acc[mi][ni][2], y1=acc[mi][ni][3];   // row s0+8
        if(tensor<2 && hcol<64){
          float inv = powf(10000.f, -(float)hcol*(1.0f/64.0f));
          float f0 = (float)p0*inv, f1 = (float)p1*inv;
          float c_0=cosf(f0), s_0=sinf(f0), c_1=cosf(f1), s_1=sinf(f1);
          float nx0 = x0*c_0 - y0*s_0, ny0 = y0*c_0 + x0*s_0;
          float nx1 = x1*c_1 - y1*s_1, ny1 = y1*c_1 + x1*s_1;
          x0=nx0; y0=ny0; x1=nx1; y1=ny1;
        }
        if(tensor==2){
          __half* vp = vo + (zz*NHD + hcol)*NS;
          vp[s0]        = __float2half_rn(x0);
          vp[s0+8]      = __float2half_rn(x1);
          vp += NS;
          vp[s0]        = __float2half_rn(y0);
          vp[s0+8]      = __float2half_rn(y1);
        }else{
          __half* dst = (tensor? ko : qo) + (zz*NS + s0)*NHD + hcol;
          *(__half2*)dst            = __floats2half2_rn(x0,y0);
          *(__half2*)(dst + 8*NHD)  = __floats2half2_rn(x1,y1);
        }
      }
    }
    return;
  }

  const long long coff = (long long)(z/cdiv)*cs1 + (long long)(z%cdiv)*cs2;
#pragma unroll
  for(int mi=0;mi<4;mi++){
    int r0 = bm*128 + wm*64 + mi*16 + gq;
#pragma unroll
    for(int ni=0;ni<4;ni++){
      int c0 = bn*128 + wn*32 + ni*8 + tg*2;
      CT* p = C + coff + (long long)r0*ldc + c0;
      st2(p,             acc[mi][ni][0], acc[mi][ni][1]);
      st2(p + 8LL*ldc,   acc[mi][ni][2], acc[mi][ni][3]);
    }
  }
}

// ---------------- fp32 -> fp16 copy ----------------
__global__ __launch_bounds__(256) void conv_half(const float* __restrict__ in, __half* __restrict__ out){
  size_t i = (size_t)(blockIdx.x*256u + threadIdx.x)*4u;
  float4 v = *(const float4*)(in+i);
  *(__half2*)(out+i)   = __floats2half2_rn(v.x,v.y);
  *(__half2*)(out+i+2) = __floats2half2_rn(v.z,v.w);
}

// ---------------- weight transpose [K,N] fp32 -> [N,K] fp16 ----------------
__global__ __launch_bounds__(256) void transpose_w(const float* __restrict__ in, __half* __restrict__ out,
                                                   int K,int N){
  __shared__ float t[32][33];
  int n0=blockIdx.x*32, k0=blockIdx.y*32;
  int tx=threadIdx.x, ty=threadIdx.y;        // 32 x 8
#pragma unroll
  for(int j=0;j<4;j++) t[ty+8*j][tx] = in[(long long)(k0+ty+8*j)*N + n0+tx];
  __syncthreads();
#pragma unroll
  for(int j=0;j<4;j++) out[(long long)(n0+ty+8*j)*K + k0+tx] = __float2half_rn(t[tx][ty+8*j]);
}

// -------- causal softmax: fp32 scores -> fp16 probs (zero-fill to 128 bdry) --
// Loops bounded by nz = ceil(zlim/256): skipped elements are exactly the
// exp(-inf)=0 / out-of-zlim ones -> bit-identical result, ~45% fewer instrs.
__global__ __launch_bounds__(256) void softmax_causal(const float* __restrict__ sc,
                                                      __half* __restrict__ pr){
  const int m=blockIdx.x, z=blockIdx.y;
  const float* row = sc + ((long long)z*NS + m)*NS;
  __half* rowp     = pr + ((long long)z*NS + m)*NS;
  const int valid=m+1;
  const int zlim=((m>>7)+1)<<7;
  const int nz=(zlim+255)>>8;        // 1..8 iterations
  const int tid=threadIdx.x;
  const float scale=0.0625f;
  float vals[8];
  float mx=-3.0e38f;
#pragma unroll
  for(int i=0;i<8;i++){
    if(i>=nz) break;
    int j=tid+(i<<8);
    float vv=-3.0e38f;
    if(j<valid) vv=row[j]*scale;
    vals[i]=vv; mx=fmaxf(mx,vv);
  }
  __shared__ float redm[8], reds[8];
#pragma unroll
  for(int o=16;o>0;o>>=1) mx=fmaxf(mx,__shfl_xor_sync(0xffffffffu,mx,o));
  if((tid&31)==0) redm[tid>>5]=mx;
  __syncthreads();
  mx=redm[0];
#pragma unroll
  for(int i=1;i<8;i++) mx=fmaxf(mx,redm[i]);
  float sum=0.f;
#pragma unroll
  for(int i=0;i<8;i++){
    if(i>=nz) break;
    float e=expf(vals[i]-mx); vals[i]=e; sum+=e;
  }
#pragma unroll
  for(int o=16;o>0;o>>=1) sum+=__shfl_xor_sync(0xffffffffu,sum,o);
  if((tid&31)==0) reds[tid>>5]=sum;
  __syncthreads();
  sum=0.f;
#pragma unroll
  for(int i=0;i<8;i++) sum+=reds[i];
  float inv=1.0f/sum;
#pragma unroll
  for(int i=0;i<8;i++){
    if(i>=nz) break;
    int j=tid+(i<<8);
    if(j<zlim) rowp[j] = __float2half_rn((j<valid)? vals[i]*inv : 0.f);
  }
}

// ---------------- launch ----------------
extern "C" void kernel_launch(void* const* d_in, const int* in_sizes, int n_in,
                              void* d_out, int out_size)
{
  const int*   pos  = (const int*)d_in[0];
  const float* hid  = (const float*)d_in[1];
  const float* wqkv = (const float*)d_in[2];
  const float* wout = (const float*)d_in[3];
  float* out = (float*)d_out;

  __half *hidh,*wqkvT,*woutT,*q,*k,*vT,*pr,*at;
  float *sc;
  cudaGetSymbolAddress((void**)&hidh, g_hid);
  cudaGetSymbolAddress((void**)&wqkvT,g_wqkvT);
  cudaGetSymbolAddress((void**)&woutT,g_woutT);
  cudaGetSymbolAddress((void**)&q,    g_q);
  cudaGetSymbolAddress((void**)&k,    g_k);
  cudaGetSymbolAddress((void**)&vT,   g_vT);
  cudaGetSymbolAddress((void**)&sc,   g_sc);
  cudaGetSymbolAddress((void**)&pr,   g_p);
  cudaGetSymbolAddress((void**)&at,   g_at);

  cudaFuncSetAttribute(gemm_fp16<float>,  cudaFuncAttributeMaxDynamicSharedMemorySize, SMEM_SZ);
  cudaFuncSetAttribute(gemm_fp16<__half>, cudaFuncAttributeMaxDynamicSharedMemorySize, SMEM_SZ);

  // 0) convert / transpose inputs to fp16
  conv_half<<<((size_t)NB*NS*ND)/1024, 256>>>(hid, hidh);
  transpose_w<<<dim3((3*ND)/32, ND/32), dim3(32,8)>>>(wqkv, wqkvT, ND, 3*ND);
  transpose_w<<<dim3(ND/32, ND/32),     dim3(32,8)>>>(wout, woutT, ND, ND);

  // 1) QKV GEMM with fused rope/split epilogue -> q, k (roped), vT (transposed)
  gemm_fp16<__half><<<dim3((3*ND)/128,(NB*NS)/128,1),256,SMEM_SZ>>>(
      hidh,wqkvT,at /*unused*/, ND, ND,ND,0, 0,0, 0,0,1, 0,1, pos,q,k,vT);

  // 2) scores = Q @ K^T (fp32 out, causal block-skip)
  gemm_fp16<float><<<dim3(NS/128,NS/128,NB*NH),256,SMEM_SZ>>>(
      q,k,sc, NHD, NHD,NHD,NS,
      (long long)NS*NHD,(long long)NS*NHD,
      (long long)NS*NS,0,1, 1,0, pos,0,0,0);

  // 3) softmax: fp32 scores -> fp16 probs (causal-bounded loops)
  softmax_causal<<<dim3(NS,NB*NH),256>>>(sc, pr);

  // 4) attn = P @ V (causal K-limit), fp16 out in [B,S,D]
  gemm_fp16<__half><<<dim3(NHD/128,NS/128,NB*NH),256,SMEM_SZ>>>(
      pr,vT,at, NS, NS,NS,ND,
      (long long)NS*NS,(long long)NHD*NS,
      (long long)NS*ND,(long long)NHD,NH, 2,0, pos,0,0,0);

  // 5) out = attn @ WoutT^T (fp32 out)
  gemm_fp16<float><<<dim3(ND/128,(NB*NS)/128,1),256,SMEM_SZ>>>(
      at,woutT,out, ND, ND,ND,ND, 0,0, 0,0,1, 0,0, pos,0,0,0);
}

// round 15
// speedup vs baseline: 1.0384x; 1.0384x over previous
#include <cuda_runtime.h>
#include <cuda_fp16.h>
#include <cstdint>

#define NB 2
#define NS 2048
#define ND 4096
#define NH 16
#define NHD 256

#define BK 64                    // K halfs per tile = 128B SW128 row
#define STAGE_M 16384            // one 128-row x 128B matrix
#define STAGE_SZ (2*STAGE_M)     // A + B = 32KB
#define NSTAGE 3
#define SMEM_SZ (NSTAGE*STAGE_SZ)   // 98304 -> 2 CTAs/SM

// ---------------- scratch (__device__ globals; no allocation) ----------------
static __device__ __half g_hid  [(size_t)NB*NS*ND];     // fp16 hidden
static __device__ __half g_wqkvT[(size_t)3*ND*ND];      // [3D, D] fp16
static __device__ __half g_woutT[(size_t)ND*ND];        // [D, D] fp16
static __device__ __half g_q    [(size_t)NB*NH*NS*NHD]; // [B,H,S,hd] fp16 (roped)
static __device__ __half g_k    [(size_t)NB*NH*NS*NHD]; // [B,H,S,hd] fp16 (roped)
static __device__ __half g_vT   [(size_t)NB*NH*NHD*NS]; // [B,H,hd,S] fp16
static __device__ float  g_sc   [(size_t)NB*NH*NS*NS];  // scores fp32
static __device__ __half g_p    [(size_t)NB*NH*NS*NS];  // probs fp16
static __device__ __half g_at   [(size_t)NB*NS*ND];     // [B,S,D] fp16

// ---------------- helpers ----------------
__device__ __forceinline__ void mmaop(float* c, const unsigned* a, const unsigned* b){
  asm volatile(
    "mma.sync.aligned.m16n8k16.row.col.f32.f16.f16.f32 "
    "{%0,%1,%2,%3},{%4,%5,%6,%7},{%8,%9},{%0,%1,%2,%3};\n"
    : "+f"(c[0]),"+f"(c[1]),"+f"(c[2]),"+f"(c[3])
    : "r"(a[0]),"r"(a[1]),"r"(a[2]),"r"(a[3]),"r"(b[0]),"r"(b[1]));
}
__device__ __forceinline__ void ldsm4(unsigned addr, unsigned* r){
  asm volatile("ldmatrix.sync.aligned.m8n8.x4.shared.b16 {%0,%1,%2,%3}, [%4];"
    : "=r"(r[0]),"=r"(r[1]),"=r"(r[2]),"=r"(r[3]) : "r"(addr));
}
__device__ __forceinline__ void cpa16(unsigned dst, const void* g){
  asm volatile("cp.async.cg.shared.global [%0],[%1],16;\n"::"r"(dst),"l"(g));
}
#define CP_COMMIT() asm volatile("cp.async.commit_group;\n")
#define CP_WAIT1()  asm volatile("cp.async.wait_group 1;\n")
__device__ __forceinline__ unsigned smem_u32(const void* p){
  unsigned a; asm("{ .reg .u64 t; cvta.to.shared.u64 t, %1; cvt.u32.u64 %0, t; }":"=r"(a):"l"(p));
  return a;
}
__device__ __forceinline__ void st2(float* p, float x, float y){
  *(float2*)p = make_float2(x,y);
}
__device__ __forceinline__ void st2(__half* p, float x, float y){
  *(__half2*)p = __floats2half2_rn(x,y);
}

// ============================================================================
// fp16 GEMM via mma.sync(m16n8k16) + ldmatrix: C = A[M,K] * B[N,K]^T, K-major
// fp16 in, fp32 accumulate. CTA 128x128 (8 warps, 64x32 warp tile), BK=64,
// SW128 swizzle, 3-stage cp.async, one __syncthreads per tile.
// causal==1: skip bn>bm.  causal==2: kend=(bm+1)*128.
// epi==1: QKV rope-split epilogue -> writes qo/ko (roped, [B,H,S,hd]) and
//         vo (transposed, [B,H,hd,S]); C unused.
// else:   C offset = (z/cdiv)*cs1 + (z%cdiv)*cs2.
// ============================================================================
template<typename CT>
__global__ void __launch_bounds__(256,2) gemm_fp16(
  const __half* __restrict__ A, const __half* __restrict__ B, CT* __restrict__ C,
  int K,int lda,int ldb,int ldc,
  long long sA,long long sB,long long cs1,long long cs2,int cdiv,
  int causal,int epi,
  const int* __restrict__ pos, __half* __restrict__ qo,
  __half* __restrict__ ko, __half* __restrict__ vo)
{
  const int bn=blockIdx.x, bm=blockIdx.y, z=blockIdx.z;
  if(causal==1 && bn>bm) return;
  int kend=K;
  if(causal==2){ int ke=(bm+1)*128; if(ke<kend) kend=ke; }
  const int nk = kend>>6;            // >= 2 for every launch here

  extern __shared__ float smem[];
  const unsigned sb = smem_u32(smem);

  const int tid=threadIdx.x, warp=tid>>5, lane=tid&31;
  const int wm=warp>>2, wn=warp&3;           // 2x4 warp grid; warp tile 64x32
  const int gq=lane>>2, tg=lane&3;

  const __half* Ab = A + (long long)z*sA + (long long)(bm*128)*lda;
  const __half* Bb = B + (long long)z*sB + (long long)(bn*128)*ldb;

  // staging: 1024 16B-chunks per matrix; thread t covers chunks {t,+256,+512,+768}
  const __half* gA[4]; const __half* gB[4]; unsigned sAo[4];
#pragma unroll
  for(int i=0;i<4;i++){
    int q=i*256+tid, row=q>>3, c=q&7;
    sAo[i] = (unsigned)(row*128 + ((c ^ (row&7))<<4));   // SW128
    gA[i]=Ab + (long long)row*lda + c*8;
    gB[i]=Bb + (long long)row*ldb + c*8;
  }

  auto stage=[&](int kt,int s){
    unsigned base = sb + s*STAGE_SZ;
#pragma unroll
    for(int i=0;i<4;i++) cpa16(base + sAo[i],           gA[i] + kt*BK);
#pragma unroll
    for(int i=0;i<4;i++) cpa16(base + STAGE_M + sAo[i], gB[i] + kt*BK);
  };

  // ldmatrix per-lane row constants
  const int lrow = lane & 15;
  const unsigned klane = lane >> 4;
  unsigned ar128[4], ar7[4], br128[2], br7[2];
#pragma unroll
  for(int mi=0;mi<4;mi++){
    int r = wm*64 + mi*16 + lrow;
    ar128[mi] = r*128; ar7[mi] = r&7;
  }
#pragma unroll
  for(int p=0;p<2;p++){
    int r = wn*32 + p*16 + lrow;
    br128[p] = r*128 + STAGE_M; br7[p] = r&7;
  }

  float acc[4][4][4];
#pragma unroll
  for(int i=0;i<4;i++)
#pragma unroll
    for(int j=0;j<4;j++)
#pragma unroll
      for(int l=0;l<4;l++) acc[i][j][l]=0.f;

  stage(0,0); CP_COMMIT();
  stage(1,1); CP_COMMIT();

  for(int kt=0; kt<nk; ++kt){
    CP_WAIT1();
    __syncthreads();

    if(kt+2<nk) stage(kt+2,(kt+2)%3);
    CP_COMMIT();

    const unsigned base = sb + (unsigned)(kt%3)*STAGE_SZ;
#pragma unroll
    for(int ks=0;ks<4;ks++){
      const unsigned ck = ks*2 + klane;
      unsigned a[4][4], br[2][4];
#pragma unroll
      for(int mi=0;mi<4;mi++)
        ldsm4(base + ar128[mi] + (((ck ^ ar7[mi]))<<4), a[mi]);
#pragma unroll
      for(int p=0;p<2;p++)
        ldsm4(base + br128[p] + (((ck ^ br7[p]))<<4), br[p]);
      unsigned b[4][2];
#pragma unroll
      for(int p=0;p<2;p++){
        b[2*p  ][0]=br[p][0]; b[2*p  ][1]=br[p][2];
        b[2*p+1][0]=br[p][1]; b[2*p+1][1]=br[p][3];
      }
#pragma unroll
      for(int mi=0;mi<4;mi++)
#pragma unroll
        for(int ni=0;ni<4;ni++)
          mmaop(acc[mi][ni], a[mi], b[ni]);
    }
  }

  if(epi){
    // ---- fused rope/split epilogue (QKV GEMM) ----
    const int cbase = bn*128;
    const int tensor = cbase >> 12;          // 0:q 1:k 2:v
    const int h = (cbase >> 8) & (NH-1);
#pragma unroll
    for(int mi=0;mi<4;mi++){
      int r0 = bm*128 + wm*64 + mi*16 + gq;  // global row; r0+8 same b
      int b0 = r0 >> 11, s0 = r0 & (NS-1);
      int p0 = pos[b0*NS+s0], p1 = pos[b0*NS+s0+8];
      const long long zz = (long long)(b0*NH + h);
#pragma unroll
      for(int ni=0;ni<4;ni++){
        int c0 = cbase + wn*32 + ni*8 + tg*2;   // even: rope pair (c0,c0+1)
        int hcol = c0 & (NHD-1);
        float x0=acc[mi][ni][0], y0=acc[mi][ni][1];   // row s0
        float x1=acc[mi][ni][2], y1=acc[mi][ni][3];   // row s0+8
        if(tensor<2 && hcol<64){
          float inv = powf(10000.f, -(float)hcol*(1.0f/64.0f));
          float f0 = (float)p0*inv, f1 = (float)p1*inv;
          float c_0=cosf(f0), s_0=sinf(f0), c_1=cosf(f1), s_1=sinf(f1);
          float nx0 = x0*c_0 - y0*s_0, ny0 = y0*c_0 + x0*s_0;
          float nx1 = x1*c_1 - y1*s_1, ny1 = y1*c_1 + x1*s_1;
          x0=nx0; y0=ny0; x1=nx1; y1=ny1;
        }
        if(tensor==2){
          __half* vp = vo + (zz*NHD + hcol)*NS;
          vp[s0]        = __float2half_rn(x0);
          vp[s0+8]      = __float2half_rn(x1);
          vp += NS;
          vp[s0]        = __float2half_rn(y0);
          vp[s0+8]      = __float2half_rn(y1);
        }else{
          __half* dst = (tensor? ko : qo) + (zz*NS + s0)*NHD + hcol;
          *(__half2*)dst            = __floats2half2_rn(x0,y0);
          *(__half2*)(dst + 8*NHD)  = __floats2half2_rn(x1,y1);
        }
      }
    }
    return;
  }

  const long long coff = (long long)(z/cdiv)*cs1 + (long long)(z%cdiv)*cs2;
#pragma unroll
  for(int mi=0;mi<4;mi++){
    int r0 = bm*128 + wm*64 + mi*16 + gq;
#pragma unroll
    for(int ni=0;ni<4;ni++){
      int c0 = bn*128 + wn*32 + ni*8 + tg*2;
      CT* p = C + coff + (long long)r0*ldc + c0;
      st2(p,             acc[mi][ni][0], acc[mi][ni][1]);
      st2(p + 8LL*ldc,   acc[mi][ni][2], acc[mi][ni][3]);
    }
  }
}

// ---------------- fp32 -> fp16 copy ----------------
__global__ __launch_bounds__(256) void conv_half(const float* __restrict__ in, __half* __restrict__ out){
  size_t i = (size_t)(blockIdx.x*256u + threadIdx.x)*4u;
  float4 v = *(const float4*)(in+i);
  *(__half2*)(out+i)   = __floats2half2_rn(v.x,v.y);
  *(__half2*)(out+i+2) = __floats2half2_rn(v.z,v.w);
}

// ---------------- weight transpose [K,N] fp32 -> [N,K] fp16 ----------------
__global__ __launch_bounds__(256) void transpose_w(const float* __restrict__ in, __half* __restrict__ out,
                                                   int K,int N){
  __shared__ float t[32][33];
  int n0=blockIdx.x*32, k0=blockIdx.y*32;
  int tx=threadIdx.x, ty=threadIdx.y;        // 32 x 8
#pragma unroll
  for(int j=0;j<4;j++) t[ty+8*j][tx] = in[(long long)(k0+ty+8*j)*N + n0+tx];
  __syncthreads();
#pragma unroll
  for(int j=0;j<4;j++) out[(long long)(n0+ty+8*j)*K + k0+tx] = __float2half_rn(t[tx][ty+8*j]);
}

// -------- causal softmax: fp32 scores -> fp16 probs (zero-fill to 128 bdry) --
// Template NI = compile-time iteration count; launched per m-segment so that
// NI*256 >= zlim for every row in the segment. Fully unrolled (no reg spill);
// bit-identical to the 8-iter version (skipped elems: exp(-inf)=0 / j>=zlim).
template<int NI>
__global__ __launch_bounds__(256) void softmax_causal(const float* __restrict__ sc,
                                                      __half* __restrict__ pr,
                                                      int m0){
  const int m=m0+blockIdx.x, z=blockIdx.y;
  const float* row = sc + ((long long)z*NS + m)*NS;
  __half* rowp     = pr + ((long long)z*NS + m)*NS;
  const int valid=m+1;
  const int zlim=((m>>7)+1)<<7;
  const int tid=threadIdx.x;
  const float scale=0.0625f;
  float vals[NI];
  float mx=-3.0e38f;
#pragma unroll
  for(int i=0;i<NI;i++){
    int j=tid+(i<<8);
    float vv=-3.0e38f;
    if(j<valid) vv=row[j]*scale;
    vals[i]=vv; mx=fmaxf(mx,vv);
  }
  __shared__ float redm[8], reds[8];
#pragma unroll
  for(int o=16;o>0;o>>=1) mx=fmaxf(mx,__shfl_xor_sync(0xffffffffu,mx,o));
  if((tid&31)==0) redm[tid>>5]=mx;
  __syncthreads();
  mx=redm[0];
#pragma unroll
  for(int i=1;i<8;i++) mx=fmaxf(mx,redm[i]);
  float sum=0.f;
#pragma unroll
  for(int i=0;i<NI;i++){ float e=expf(vals[i]-mx); vals[i]=e; sum+=e; }
#pragma unroll
  for(int o=16;o>0;o>>=1) sum+=__shfl_xor_sync(0xffffffffu,sum,o);
  if((tid&31)==0) reds[tid>>5]=sum;
  __syncthreads();
  sum=0.f;
#pragma unroll
  for(int i=0;i<8;i++) sum+=reds[i];
  float inv=1.0f/sum;
#pragma unroll
  for(int i=0;i<NI;i++){
    int j=tid+(i<<8);
    if(j<zlim) rowp[j] = __float2half_rn((j<valid)? vals[i]*inv : 0.f);
  }
}

// ---------------- launch ----------------
extern "C" void kernel_launch(void* const* d_in, const int* in_sizes, int n_in,
                              void* d_out, int out_size)
{
  const int*   pos  = (const int*)d_in[0];
  const float* hid  = (const float*)d_in[1];
  const float* wqkv = (const float*)d_in[2];
  const float* wout = (const float*)d_in[3];
  float* out = (float*)d_out;

  __half *hidh,*wqkvT,*woutT,*q,*k,*vT,*pr,*at;
  float *sc;
  cudaGetSymbolAddress((void**)&hidh, g_hid);
  cudaGetSymbolAddress((void**)&wqkvT,g_wqkvT);
  cudaGetSymbolAddress((void**)&woutT,g_woutT);
  cudaGetSymbolAddress((void**)&q,    g_q);
  cudaGetSymbolAddress((void**)&k,    g_k);
  cudaGetSymbolAddress((void**)&vT,   g_vT);
  cudaGetSymbolAddress((void**)&sc,   g_sc);
  cudaGetSymbolAddress((void**)&pr,   g_p);
  cudaGetSymbolAddress((void**)&at,   g_at);

  cudaFuncSetAttribute(gemm_fp16<float>,  cudaFuncAttributeMaxDynamicSharedMemorySize, SMEM_SZ);
  cudaFuncSetAttribute(gemm_fp16<__half>, cudaFuncAttributeMaxDynamicSharedMemorySize, SMEM_SZ);

  // 0) convert / transpose inputs to fp16
  conv_half<<<((size_t)NB*NS*ND)/1024, 256>>>(hid, hidh);
  transpose_w<<<dim3((3*ND)/32, ND/32), dim3(32,8)>>>(wqkv, wqkvT, ND, 3*ND);
  transpose_w<<<dim3(ND/32, ND/32),     dim3(32,8)>>>(wout, woutT, ND, ND);

  // 1) QKV GEMM with fused rope/split epilogue -> q, k (roped), vT (transposed)
  gemm_fp16<__half><<<dim3((3*ND)/128,(NB*NS)/128,1),256,SMEM_SZ>>>(
      hidh,wqkvT,at /*unused*/, ND, ND,ND,0, 0,0, 0,0,1, 0,1, pos,q,k,vT);

  // 2) scores = Q @ K^T (fp32 out, causal block-skip)
  gemm_fp16<float><<<dim3(NS/128,NS/128,NB*NH),256,SMEM_SZ>>>(
      q,k,sc, NHD, NHD,NHD,NS,
      (long long)NS*NHD,(long long)NS*NHD,
      (long long)NS*NS,0,1, 1,0, pos,0,0,0);

  // 3) softmax: fp32 scores -> fp16 probs; 4 m-segments, compile-time unroll
  softmax_causal<2><<<dim3(512,NB*NH),256>>>(sc, pr, 0);
  softmax_causal<4><<<dim3(512,NB*NH),256>>>(sc, pr, 512);
  softmax_causal<6><<<dim3(512,NB*NH),256>>>(sc, pr, 1024);
  softmax_causal<8><<<dim3(512,NB*NH),256>>>(sc, pr, 1536);

  // 4) attn = P @ V (causal K-limit), fp16 out in [B,S,D]
  gemm_fp16<__half><<<dim3(NHD/128,NS/128,NB*NH),256,SMEM_SZ>>>(
      pr,vT,at, NS, NS,NS,ND,
      (long long)NS*NS,(long long)NHD*NS,
      (long long)NS*ND,(long long)NHD,NH, 2,0, pos,0,0,0);

  // 5) out = attn @ WoutT^T (fp32 out)
  gemm_fp16<float><<<dim3(ND/128,(NB*NS)/128,1),256,SMEM_SZ>>>(
      at,woutT,out, ND, ND,ND,ND, 0,0, 0,0,1, 0,0, pos,0,0,0);
}

// round 16
// speedup vs baseline: 1.0634x; 1.0241x over previous
#include <cuda_runtime.h>
#include <cuda_fp16.h>
#include <cstdint>

#define NB 2
#define NS 2048
#define ND 4096
#define NH 16
#define NHD 256

#define BK 64                    // K halfs per tile = 128B SW128 row
#define STAGE_M 16384            // one 128-row x 128B matrix
#define STAGE_SZ (2*STAGE_M)     // A + B = 32KB
#define NSTAGE 3
#define SMEM_SZ (NSTAGE*STAGE_SZ)   // 98304 -> 2 CTAs/SM

// flash smem map (bytes)
#define SQ    0
#define SKo   65536
#define SVo   131072
#define SPo   196608
#define SSTAT 229376
#define FSMEM 231424

// ---------------- scratch (__device__ globals; no allocation) ----------------
static __device__ __half g_hid  [(size_t)NB*NS*ND];     // fp16 hidden
static __device__ __half g_wqkvT[(size_t)3*ND*ND];      // [3D, D] fp16
static __device__ __half g_woutT[(size_t)ND*ND];        // [D, D] fp16
static __device__ __half g_q    [(size_t)NB*NH*NS*NHD]; // [B,H,S,hd] fp16 (roped)
static __device__ __half g_k    [(size_t)NB*NH*NS*NHD]; // [B,H,S,hd] fp16 (roped)
static __device__ __half g_vT   [(size_t)NB*NH*NHD*NS]; // [B,H,hd,S] fp16
static __device__ __half g_at   [(size_t)NB*NS*ND];     // [B,S,D] fp16

// ---------------- helpers ----------------
__device__ __forceinline__ void mmaop(float* c, const unsigned* a, const unsigned* b){
  asm volatile(
    "mma.sync.aligned.m16n8k16.row.col.f32.f16.f16.f32 "
    "{%0,%1,%2,%3},{%4,%5,%6,%7},{%8,%9},{%0,%1,%2,%3};\n"
    : "+f"(c[0]),"+f"(c[1]),"+f"(c[2]),"+f"(c[3])
    : "r"(a[0]),"r"(a[1]),"r"(a[2]),"r"(a[3]),"r"(b[0]),"r"(b[1]));
}
__device__ __forceinline__ void ldsm4(unsigned addr, unsigned* r){
  asm volatile("ldmatrix.sync.aligned.m8n8.x4.shared.b16 {%0,%1,%2,%3}, [%4];"
    : "=r"(r[0]),"=r"(r[1]),"=r"(r[2]),"=r"(r[3]) : "r"(addr));
}
__device__ __forceinline__ void cpa16(unsigned dst, const void* g){
  asm volatile("cp.async.cg.shared.global [%0],[%1],16;\n"::"r"(dst),"l"(g));
}
#define CP_COMMIT() asm volatile("cp.async.commit_group;\n")
#define CP_WAIT1()  asm volatile("cp.async.wait_group 1;\n")
#define CP_WAIT0()  asm volatile("cp.async.wait_group 0;\n")
__device__ __forceinline__ unsigned smem_u32(const void* p){
  unsigned a; asm("{ .reg .u64 t; cvta.to.shared.u64 t, %1; cvt.u32.u64 %0, t; }":"=r"(a):"l"(p));
  return a;
}
__device__ __forceinline__ void st2(float* p, float x, float y){
  *(float2*)p = make_float2(x,y);
}
__device__ __forceinline__ void st2(__half* p, float x, float y){
  *(__half2*)p = __floats2half2_rn(x,y);
}

// ============================================================================
// fp16 GEMM (unchanged from best kernel): C = A[M,K] * B[N,K]^T, K-major.
// ============================================================================
template<typename CT>
__global__ void __launch_bounds__(256,2) gemm_fp16(
  const __half* __restrict__ A, const __half* __restrict__ B, CT* __restrict__ C,
  int K,int lda,int ldb,int ldc,
  long long sA,long long sB,long long cs1,long long cs2,int cdiv,
  int causal,int epi,
  const int* __restrict__ pos, __half* __restrict__ qo,
  __half* __restrict__ ko, __half* __restrict__ vo)
{
  const int bn=blockIdx.x, bm=blockIdx.y, z=blockIdx.z;
  if(causal==1 && bn>bm) return;
  int kend=K;
  if(causal==2){ int ke=(bm+1)*128; if(ke<kend) kend=ke; }
  const int nk = kend>>6;

  extern __shared__ float smemf[];
  const unsigned sb = smem_u32(smemf);

  const int tid=threadIdx.x, warp=tid>>5, lane=tid&31;
  const int wm=warp>>2, wn=warp&3;
  const int gq=lane>>2, tg=lane&3;

  const __half* Ab = A + (long long)z*sA + (long long)(bm*128)*lda;
  const __half* Bb = B + (long long)z*sB + (long long)(bn*128)*ldb;

  const __half* gA[4]; const __half* gB[4]; unsigned sAo[4];
#pragma unroll
  for(int i=0;i<4;i++){
    int q=i*256+tid, row=q>>3, c=q&7;
    sAo[i] = (unsigned)(row*128 + ((c ^ (row&7))<<4));
    gA[i]=Ab + (long long)row*lda + c*8;
    gB[i]=Bb + (long long)row*ldb + c*8;
  }

  auto stage=[&](int kt,int s){
    unsigned base = sb + s*STAGE_SZ;
#pragma unroll
    for(int i=0;i<4;i++) cpa16(base + sAo[i],           gA[i] + kt*BK);
#pragma unroll
    for(int i=0;i<4;i++) cpa16(base + STAGE_M + sAo[i], gB[i] + kt*BK);
  };

  const int lrow = lane & 15;
  const unsigned klane = lane >> 4;
  unsigned ar128[4], ar7[4], br128[2], br7[2];
#pragma unroll
  for(int mi=0;mi<4;mi++){
    int r = wm*64 + mi*16 + lrow;
    ar128[mi] = r*128; ar7[mi] = r&7;
  }
#pragma unroll
  for(int p=0;p<2;p++){
    int r = wn*32 + p*16 + lrow;
    br128[p] = r*128 + STAGE_M; br7[p] = r&7;
  }

  float acc[4][4][4];
#pragma unroll
  for(int i=0;i<4;i++)
#pragma unroll
    for(int j=0;j<4;j++)
#pragma unroll
      for(int l=0;l<4;l++) acc[i][j][l]=0.f;

  stage(0,0); CP_COMMIT();
  stage(1,1); CP_COMMIT();

  for(int kt=0; kt<nk; ++kt){
    CP_WAIT1();
    __syncthreads();

    if(kt+2<nk) stage(kt+2,(kt+2)%3);
    CP_COMMIT();

    const unsigned base = sb + (unsigned)(kt%3)*STAGE_SZ;
#pragma unroll
    for(int ks=0;ks<4;ks++){
      const unsigned ck = ks*2 + klane;
      unsigned a[4][4], br[2][4];
#pragma unroll
      for(int mi=0;mi<4;mi++)
        ldsm4(base + ar128[mi] + (((ck ^ ar7[mi]))<<4), a[mi]);
#pragma unroll
      for(int p=0;p<2;p++)
        ldsm4(base + br128[p] + (((ck ^ br7[p]))<<4), br[p]);
      unsigned b[4][2];
#pragma unroll
      for(int p=0;p<2;p++){
        b[2*p  ][0]=br[p][0]; b[2*p  ][1]=br[p][2];
        b[2*p+1][0]=br[p][1]; b[2*p+1][1]=br[p][3];
      }
#pragma unroll
      for(int mi=0;mi<4;mi++)
#pragma unroll
        for(int ni=0;ni<4;ni++)
          mmaop(acc[mi][ni], a[mi], b[ni]);
    }
  }

  if(epi){
    const int cbase = bn*128;
    const int tensor = cbase >> 12;
    const int h = (cbase >> 8) & (NH-1);
#pragma unroll
    for(int mi=0;mi<4;mi++){
      int r0 = bm*128 + wm*64 + mi*16 + gq;
      int b0 = r0 >> 11, s0 = r0 & (NS-1);
      int p0 = pos[b0*NS+s0], p1 = pos[b0*NS+s0+8];
      const long long zz = (long long)(b0*NH + h);
#pragma unroll
      for(int ni=0;ni<4;ni++){
        int c0 = cbase + wn*32 + ni*8 + tg*2;
        int hcol = c0 & (NHD-1);
        float x0=acc[mi][ni][0], y0=acc[mi][ni][1];
        float x1=acc[mi][ni][2], y1=acc[mi][ni][3];
        if(tensor<2 && hcol<64){
          float inv = powf(10000.f, -(float)hcol*(1.0f/64.0f));
          float f0 = (float)p0*inv, f1 = (float)p1*inv;
          float c_0=cosf(f0), s_0=sinf(f0), c_1=cosf(f1), s_1=sinf(f1);
          float nx0 = x0*c_0 - y0*s_0, ny0 = y0*c_0 + x0*s_0;
          float nx1 = x1*c_1 - y1*s_1, ny1 = y1*c_1 + x1*s_1;
          x0=nx0; y0=ny0; x1=nx1; y1=ny1;
        }
        if(tensor==2){
          __half* vp = vo + (zz*NHD + hcol)*NS;
          vp[s0]   = __float2half_rn(x0);
          vp[s0+8] = __float2half_rn(x1);
          vp += NS;
          vp[s0]   = __float2half_rn(y0);
          vp[s0+8] = __float2half_rn(y1);
        }else{
          __half* dst = (tensor? ko : qo) + (zz*NS + s0)*NHD + hcol;
          *(__half2*)dst            = __floats2half2_rn(x0,y0);
          *(__half2*)(dst + 8*NHD)  = __floats2half2_rn(x1,y1);
        }
      }
    }
    return;
  }

  const long long coff = (long long)(z/cdiv)*cs1 + (long long)(z%cdiv)*cs2;
#pragma unroll
  for(int mi=0;mi<4;mi++){
    int r0 = bm*128 + wm*64 + mi*16 + gq;
#pragma unroll
    for(int ni=0;ni<4;ni++){
      int c0 = bn*128 + wn*32 + ni*8 + tg*2;
      CT* p = C + coff + (long long)r0*ldc + c0;
      st2(p,             acc[mi][ni][0], acc[mi][ni][1]);
      st2(p + 8LL*ldc,   acc[mi][ni][2], acc[mi][ni][3]);
    }
  }
}

// ============================================================================
// Flash attention: per CTA 128 query rows x hd=256; loop over 128-key tiles.
// Q persistent smem; K/VT streamed via cp.async; P via smem; online softmax.
// Grid (16 bm, 32 z), 256 thr, 1 CTA/SM. Writes at [B,S,D] fp16.
// ============================================================================
__global__ void __launch_bounds__(256,1) flash_attn(
  const __half* __restrict__ q, const __half* __restrict__ k,
  const __half* __restrict__ vT, __half* __restrict__ at)
{
  const int bm = (int)(gridDim.x-1) - (int)blockIdx.x;   // big tiles first
  const int z = blockIdx.y;
  extern __shared__ char smem[];
  const unsigned sb = smem_u32(smem);
  float* stats = (float*)(smem + SSTAT);

  const int tid=threadIdx.x, warp=tid>>5, lane=tid&31;
  const int wm=warp>>2, wn=warp&3, gq=lane>>2, tg=lane&3;
  const int lrow=lane&15; const unsigned klane=lane>>4;

  unsigned ar128[4], ar7[4], bs128[2], bs7[2], bv128[4], bv7[4];
#pragma unroll
  for(int mi=0;mi<4;mi++){ int r=wm*64+mi*16+lrow; ar128[mi]=r*128; ar7[mi]=r&7; }
#pragma unroll
  for(int p=0;p<2;p++){ int r=wn*32+p*16+lrow; bs128[p]=r*128; bs7[p]=r&7; }
#pragma unroll
  for(int p=0;p<4;p++){ int r=wn*64+p*16+lrow; bv128[p]=r*128; bv7[p]=r&7; }

  int r16[4], c16[4]; unsigned so16[4];
#pragma unroll
  for(int i=0;i<4;i++){ int qq=i*256+tid, r=qq>>3, c=qq&7;
    r16[i]=r; c16[i]=c; so16[i]=(unsigned)(r*128+((c^(r&7))<<4)); }
  int r32[8], c32[8]; unsigned so32[8];
#pragma unroll
  for(int i=0;i<8;i++){ int qq=i*256+tid, r=qq>>3, c=qq&7;
    r32[i]=r; c32[i]=c; so32[i]=(unsigned)(r*128+((c^(r&7))<<4)); }

  const __half* Qg = q  + ((long long)z*NS + bm*128)*NHD;
  const __half* Kg = k  + (long long)z*NS*NHD;
  const __half* Vg = vT + (long long)z*NHD*NS;

  // preamble: Q + K0 (group), VT0 (group)
#pragma unroll
  for(int c=0;c<4;c++)
#pragma unroll
    for(int i=0;i<4;i++)
      cpa16(sb+SQ+c*16384+so16[i], Qg + (long long)r16[i]*NHD + c*64 + c16[i]*8);
#pragma unroll
  for(int c=0;c<4;c++)
#pragma unroll
    for(int i=0;i<4;i++)
      cpa16(sb+SKo+c*16384+so16[i], Kg + (long long)r16[i]*NHD + c*64 + c16[i]*8);
  CP_COMMIT();
#pragma unroll
  for(int c=0;c<2;c++)
#pragma unroll
    for(int i=0;i<8;i++)
      cpa16(sb+SVo+c*32768+so32[i], Vg + (long long)r32[i]*NS + c*64 + c32[i]*8);
  CP_COMMIT();

  float accO[4][8][4];
#pragma unroll
  for(int i=0;i<4;i++)
#pragma unroll
    for(int j2=0;j2<8;j2++)
#pragma unroll
      for(int l=0;l<4;l++) accO[i][j2][l]=0.f;
  float mst[4][2], lst[4][2];
#pragma unroll
  for(int i=0;i<4;i++){ mst[i][0]=mst[i][1]=-1e30f; lst[i][0]=lst[i][1]=0.f; }

  for(int j=0;j<=bm;j++){
    CP_WAIT1(); __syncthreads();          // K_j (and Q on first iter) ready

    // ---- scores = Q @ K_j^T (128x128, scaled) ----
    float accS[4][4][4];
#pragma unroll
    for(int i=0;i<4;i++)
#pragma unroll
      for(int n2=0;n2<4;n2++)
#pragma unroll
        for(int l=0;l<4;l++) accS[i][n2][l]=0.f;
#pragma unroll
    for(int ch=0;ch<4;ch++){
      unsigned qb=sb+SQ+ch*16384, kb=sb+SKo+ch*16384;
#pragma unroll
      for(int ks=0;ks<4;ks++){
        unsigned ck=ks*2+klane;
        unsigned a[4][4], br[2][4];
#pragma unroll
        for(int mi=0;mi<4;mi++) ldsm4(qb+ar128[mi]+((ck^ar7[mi])<<4), a[mi]);
#pragma unroll
        for(int p=0;p<2;p++)    ldsm4(kb+bs128[p]+((ck^bs7[p])<<4), br[p]);
        unsigned b[4][2];
#pragma unroll
        for(int p=0;p<2;p++){
          b[2*p  ][0]=br[p][0]; b[2*p  ][1]=br[p][2];
          b[2*p+1][0]=br[p][1]; b[2*p+1][1]=br[p][3];
        }
#pragma unroll
        for(int mi=0;mi<4;mi++)
#pragma unroll
          for(int ni=0;ni<4;ni++)
            mmaop(accS[mi][ni], a[mi], b[ni]);
      }
    }
#pragma unroll
    for(int mi=0;mi<4;mi++)
#pragma unroll
      for(int ni=0;ni<4;ni++)
#pragma unroll
        for(int l=0;l<4;l++) accS[mi][ni][l]*=0.0625f;
    if(j==bm){                             // causal mask on diagonal tile
#pragma unroll
      for(int mi=0;mi<4;mi++)
#pragma unroll
        for(int ni=0;ni<4;ni++)
#pragma unroll
          for(int l=0;l<4;l++){
            int row = wm*64+mi*16+gq+((l&2)?8:0);
            int col = wn*32+ni*8+tg*2+(l&1);
            if(col>row) accS[mi][ni][l]=-1e30f;
          }
    }

    // ---- online softmax ----
    float f_[4][2], ps_[4][2];
#pragma unroll
    for(int mi=0;mi<4;mi++)
#pragma unroll
      for(int hh=0;hh<2;hh++){
        int rowl = wm*64+mi*16+hh*8+gq;
        float rm=-1e30f;
#pragma unroll
        for(int ni=0;ni<4;ni++){
          rm=fmaxf(rm,accS[mi][ni][hh*2]); rm=fmaxf(rm,accS[mi][ni][hh*2+1]);
        }
        rm=fmaxf(rm,__shfl_xor_sync(0xffffffffu,rm,1));
        rm=fmaxf(rm,__shfl_xor_sync(0xffffffffu,rm,2));
        if(tg==0) stats[wn*128+rowl]=rm;
      }
    __syncthreads();
#pragma unroll
    for(int mi=0;mi<4;mi++)
#pragma unroll
      for(int hh=0;hh<2;hh++){
        int rowl = wm*64+mi*16+hh*8+gq;
        float tm=fmaxf(fmaxf(stats[rowl],stats[128+rowl]),
                       fmaxf(stats[256+rowl],stats[384+rowl]));
        float mo=mst[mi][hh], mn=fmaxf(mo,tm);
        float f=expf(mo-mn);
        mst[mi][hh]=mn; f_[mi][hh]=f;
        float ps=0.f;
#pragma unroll
        for(int ni=0;ni<4;ni++){
          float p0=expf(accS[mi][ni][hh*2]  -mn);
          float p1=expf(accS[mi][ni][hh*2+1]-mn);
          accS[mi][ni][hh*2]=p0; accS[mi][ni][hh*2+1]=p1; ps+=p0+p1;
        }
        ps+=__shfl_xor_sync(0xffffffffu,ps,1);
        ps+=__shfl_xor_sync(0xffffffffu,ps,2);
        ps_[mi][hh]=ps;
      }
    __syncthreads();
#pragma unroll
    for(int mi=0;mi<4;mi++)
#pragma unroll
      for(int hh=0;hh<2;hh++){
        int rowl = wm*64+mi*16+hh*8+gq;
        if(tg==0) stats[wn*128+rowl]=ps_[mi][hh];
      }
    __syncthreads();
#pragma unroll
    for(int mi=0;mi<4;mi++)
#pragma unroll
      for(int hh=0;hh<2;hh++){
        int rowl = wm*64+mi*16+hh*8+gq;
        float ts=stats[rowl]+stats[128+rowl]+stats[256+rowl]+stats[384+rowl];
        float f=f_[mi][hh];
        lst[mi][hh]=lst[mi][hh]*f+ts;
#pragma unroll
        for(int ni=0;ni<8;ni++){
          accO[mi][ni][hh*2]*=f; accO[mi][ni][hh*2+1]*=f;
        }
      }

    // ---- P -> smem (fp16, SW128 per 64-col chunk) ----
#pragma unroll
    for(int mi=0;mi<4;mi++)
#pragma unroll
      for(int hh=0;hh<2;hh++){
        int rowl = wm*64+mi*16+hh*8+gq;
#pragma unroll
        for(int ni=0;ni<4;ni++){
          int c = wn*32+ni*8+tg*2;
          int c64=c&63, bo=c64*2;
          unsigned off = SPo + (unsigned)(c>>6)*16384 + rowl*128
                       + (((bo>>4)^(rowl&7))<<4) + (bo&15);
          *(__half2*)(smem+off) =
            __floats2half2_rn(accS[mi][ni][hh*2], accS[mi][ni][hh*2+1]);
        }
      }

    // prefetch K_{j+1} (clamped)
    int jn = (j<bm)? j+1 : bm;
#pragma unroll
    for(int c=0;c<4;c++)
#pragma unroll
      for(int i=0;i<4;i++)
        cpa16(sb+SKo+c*16384+so16[i],
              Kg + (long long)(jn*128+r16[i])*NHD + c*64 + c16[i]*8);
    CP_COMMIT();

    CP_WAIT1(); __syncthreads();          // VT_j ready, P visible

    // ---- accO += P @ VT_j ----
#pragma unroll
    for(int ch=0;ch<2;ch++){
      unsigned pb=sb+SPo+ch*16384, vb=sb+SVo+ch*32768;
#pragma unroll
      for(int ks=0;ks<4;ks++){
        unsigned ck=ks*2+klane;
        unsigned a[4][4], brv[4][4];
#pragma unroll
        for(int mi=0;mi<4;mi++) ldsm4(pb+ar128[mi]+((ck^ar7[mi])<<4), a[mi]);
#pragma unroll
        for(int p=0;p<4;p++)    ldsm4(vb+bv128[p]+((ck^bv7[p])<<4), brv[p]);
        unsigned b[8][2];
#pragma unroll
        for(int p=0;p<4;p++){
          b[2*p  ][0]=brv[p][0]; b[2*p  ][1]=brv[p][2];
          b[2*p+1][0]=brv[p][1]; b[2*p+1][1]=brv[p][3];
        }
#pragma unroll
        for(int mi=0;mi<4;mi++)
#pragma unroll
          for(int ni=0;ni<8;ni++)
            mmaop(accO[mi][ni], a[mi], b[ni]);
      }
    }
    __syncthreads();                      // all VT/P reads done

    // prefetch VT_{j+1} (clamped)
#pragma unroll
    for(int c=0;c<2;c++)
#pragma unroll
      for(int i=0;i<8;i++)
        cpa16(sb+SVo+c*32768+so32[i],
              Vg + (long long)r32[i]*NS + jn*128 + c*64 + c32[i]*8);
    CP_COMMIT();
  }

  CP_WAIT0();                             // drain before exit

  // ---- epilogue: normalize and write at [B,S,D] ----
  const int b0=z>>4, head=z&15;
#pragma unroll
  for(int mi=0;mi<4;mi++)
#pragma unroll
    for(int hh=0;hh<2;hh++){
      int rowl = wm*64+mi*16+hh*8+gq;
      int s = bm*128+rowl;
      float inv = 1.f/lst[mi][hh];
#pragma unroll
      for(int ni=0;ni<8;ni++){
        int c = wn*64+ni*8+tg*2;
        *(__half2*)(at + (long long)(b0*NS+s)*ND + head*NHD + c) =
          __floats2half2_rn(accO[mi][ni][hh*2]*inv, accO[mi][ni][hh*2+1]*inv);
      }
    }
}

// ---------------- fp32 -> fp16 copy ----------------
__global__ __launch_bounds__(256) void conv_half(const float* __restrict__ in, __half* __restrict__ out){
  size_t i = (size_t)(blockIdx.x*256u + threadIdx.x)*4u;
  float4 v = *(const float4*)(in+i);
  *(__half2*)(out+i)   = __floats2half2_rn(v.x,v.y);
  *(__half2*)(out+i+2) = __floats2half2_rn(v.z,v.w);
}

// ---------------- weight transpose [K,N] fp32 -> [N,K] fp16 ----------------
__global__ __launch_bounds__(256) void transpose_w(const float* __restrict__ in, __half* __restrict__ out,
                                                   int K,int N){
  __shared__ float t[32][33];
  int n0=blockIdx.x*32, k0=blockIdx.y*32;
  int tx=threadIdx.x, ty=threadIdx.y;
#pragma unroll
  for(int j=0;j<4;j++) t[ty+8*j][tx] = in[(long long)(k0+ty+8*j)*N + n0+tx];
  __syncthreads();
#pragma unroll
  for(int j=0;j<4;j++) out[(long long)(n0+ty+8*j)*K + k0+tx] = __float2half_rn(t[tx][ty+8*j]);
}

// ---------------- launch ----------------
extern "C" void kernel_launch(void* const* d_in, const int* in_sizes, int n_in,
                              void* d_out, int out_size)
{
  const int*   pos  = (const int*)d_in[0];
  const float* hid  = (const float*)d_in[1];
  const float* wqkv = (const float*)d_in[2];
  const float* wout = (const float*)d_in[3];
  float* out = (float*)d_out;

  __half *hidh,*wqkvT,*woutT,*q,*k,*vT,*at;
  cudaGetSymbolAddress((void**)&hidh, g_hid);
  cudaGetSymbolAddress((void**)&wqkvT,g_wqkvT);
  cudaGetSymbolAddress((void**)&woutT,g_woutT);
  cudaGetSymbolAddress((void**)&q,    g_q);
  cudaGetSymbolAddress((void**)&k,    g_k);
  cudaGetSymbolAddress((void**)&vT,   g_vT);
  cudaGetSymbolAddress((void**)&at,   g_at);

  cudaFuncSetAttribute(gemm_fp16<float>,  cudaFuncAttributeMaxDynamicSharedMemorySize, SMEM_SZ);
  cudaFuncSetAttribute(gemm_fp16<__half>, cudaFuncAttributeMaxDynamicSharedMemorySize, SMEM_SZ);
  cudaFuncSetAttribute(flash_attn,        cudaFuncAttributeMaxDynamicSharedMemorySize, FSMEM);

  // 0) convert / transpose inputs to fp16
  conv_half<<<((size_t)NB*NS*ND)/1024, 256>>>(hid, hidh);
  transpose_w<<<dim3((3*ND)/32, ND/32), dim3(32,8)>>>(wqkv, wqkvT, ND, 3*ND);
  transpose_w<<<dim3(ND/32, ND/32),     dim3(32,8)>>>(wout, woutT, ND, ND);

  // 1) QKV GEMM with fused rope/split epilogue -> q, k (roped), vT (transposed)
  gemm_fp16<__half><<<dim3((3*ND)/128,(NB*NS)/128,1),256,SMEM_SZ>>>(
      hidh,wqkvT,at /*unused*/, ND, ND,ND,0, 0,0, 0,0,1, 0,1, pos,q,k,vT);

  // 2) flash attention: scores+softmax+PV fused -> at [B,S,D] fp16
  flash_attn<<<dim3(NS/128, NB*NH), 256, FSMEM>>>(q, k, vT, at);

  // 3) out = attn @ WoutT^T (fp32 out)
  gemm_fp16<float><<<dim3(ND/128,(NB*NS)/128,1),256,SMEM_SZ>>>(
      at,woutT,out, ND, ND,ND,ND, 0,0, 0,0,1, 0,0, pos,0,0,0);
}